// round 5
// baseline (speedup 1.0000x reference)
#include <cuda_runtime.h>
#include <cuda_fp16.h>
#include <math.h>
#include <stdint.h>

// ===========================================================================
// out[M,N] = x[M,K] @ (w * nm_mask(w))[N,K]^T + bias[N]
// M=16384, N=2048, K=2048 fp32.
// Sparse tensor cores: W is 2:4 along K after masking -> mma.sp m16n8k32.
// Compute out^T[N,M] = Wc (sparse A) @ x^T (B), transpose in epilogue.
// ===========================================================================

__device__ __half   g_xh[16384 * 2048];          // x as fp16
__device__ __half   g_wc[2048 * 1024];           // compressed W (2 of 4 kept)
__device__ uint8_t  g_m4[2048 * 512];            // per-group 4-bit meta (byte)
__device__ uint32_t g_meta[128 * 8 * 128];       // packed E words

// ---------------- helpers ---------------------------------------------------
__device__ __forceinline__ uint32_t smem_u32(const void* p) {
    uint32_t a;
    asm("{ .reg .u64 t; cvta.to.shared.u64 t, %1; cvt.u32.u64 %0, t; }"
        : "=r"(a) : "l"(p));
    return a;
}
__device__ __forceinline__ void cp16(uint32_t sm, const void* g) {
    asm volatile("cp.async.cg.shared.global [%0], [%1], 16;" :: "r"(sm), "l"(g));
}
#define CP_COMMIT() asm volatile("cp.async.commit_group;" ::: "memory")
#define CP_WAIT2()  asm volatile("cp.async.wait_group 2;"  ::: "memory")
#define CP_WAIT0()  asm volatile("cp.async.wait_group 0;"  ::: "memory")

__device__ __forceinline__ void ldm4(uint32_t r[4], uint32_t addr) {
    asm volatile("ldmatrix.sync.aligned.m8n8.x4.shared.b16 {%0,%1,%2,%3}, [%4];"
                 : "=r"(r[0]), "=r"(r[1]), "=r"(r[2]), "=r"(r[3]) : "r"(addr));
}
// sparse MMA: A 16x32 (2:4, compressed 16x16) x B 32x8 -> C 16x8, fp32 accum
__device__ __forceinline__ void mma_sp(float c[4], const uint32_t a[4],
                                       const uint32_t b[4], uint32_t e) {
    asm volatile(
        "mma.sp.sync.aligned.m16n8k32.row.col.f32.f16.f16.f32 "
        "{%0,%1,%2,%3}, {%4,%5,%6,%7}, {%8,%9,%10,%11}, {%0,%1,%2,%3}, %12, 0x0;"
        : "+f"(c[0]), "+f"(c[1]), "+f"(c[2]), "+f"(c[3])
        : "r"(a[0]), "r"(a[1]), "r"(a[2]), "r"(a[3]),
          "r"(b[0]), "r"(b[1]), "r"(b[2]), "r"(b[3]), "r"(e));
}

// ---------------- GEMM config ----------------------------------------------
// mma-M dim = N (W rows), mma-N dim = M (x rows)
#define BW 128               // W rows per CTA
#define BX 256               // x rows per CTA
#define NTH 256
#define NSTAGE 4
#define A_RS   80            // compressed-A smem row stride (conflict-free)
#define STG_A  0             // 128 rows x 80 B = 10240
#define STG_B  10240         // 256 rows x 128 B = 32768
#define STAGE_SZ 43008
#define SMEM_TOTAL (NSTAGE * STAGE_SZ)   // 172032

// ===========================================================================
// Kernel 1: 2:4 mask (stable-argsort) -> compressed vals + 4-bit meta
// ===========================================================================
__global__ void prep_w_kernel(const float* __restrict__ w, int n_groups) {
    int g = blockIdx.x * blockDim.x + threadIdx.x;
    if (g >= n_groups) return;
    float4 v = reinterpret_cast<const float4*>(w)[g];
    float vals[4] = {v.x, v.y, v.z, v.w};
    float a[4] = {fabsf(v.x), fabsf(v.y), fabsf(v.z), fabsf(v.w)};
    int z1 = 0;
    #pragma unroll
    for (int i = 1; i < 4; i++) if (a[i] < a[z1]) z1 = i;
    a[z1] = INFINITY;
    int z2 = 0;
    #pragma unroll
    for (int i = 1; i < 4; i++) if (a[i] < a[z2]) z2 = i;

    // kept indices in ascending order
    int i0 = -1, i1 = -1;
    #pragma unroll
    for (int i = 0; i < 4; i++) {
        if (i == z1 || i == z2) continue;
        if (i0 < 0) i0 = i; else i1 = i;
    }
    __half2 hv(__float2half(vals[i0]), __float2half(vals[i1]));
    reinterpret_cast<uint32_t*>(g_wc)[g] = *reinterpret_cast<uint32_t*>(&hv);
    g_m4[g] = (uint8_t)(i0 | (i1 << 2));
}

// ===========================================================================
// Kernel 2: pack metadata words.
// E for lane pair: low16 = row r (4 nibbles = k16 chunk), high16 = row r+8.
// g_meta[(tile*8 + r)*128 + c]  (tile = W row / 16, c = k16 chunk)
// ===========================================================================
__global__ void pack_meta_kernel(int n_words) {
    int t = blockIdx.x * blockDim.x + threadIdx.x;
    if (t >= n_words) return;
    int c = t & 127;
    int r = (t >> 7) & 7;
    int tile = t >> 10;
    int rowA = tile * 16 + r;
    int rowB = rowA + 8;
    uint32_t wa = *reinterpret_cast<const uint32_t*>(g_m4 + rowA * 512 + c * 4);
    uint32_t wb = *reinterpret_cast<const uint32_t*>(g_m4 + rowB * 512 + c * 4);
    uint32_t lo = (wa & 0xF) | ((wa >> 4) & 0xF0) | ((wa >> 8) & 0xF00) | ((wa >> 12) & 0xF000);
    uint32_t hi = (wb & 0xF) | ((wb >> 4) & 0xF0) | ((wb >> 8) & 0xF00) | ((wb >> 12) & 0xF000);
    g_meta[t] = lo | (hi << 16);
}

// ===========================================================================
// Kernel 3: fp16 convert of x
// ===========================================================================
__global__ void prep_x_kernel(const float* __restrict__ x, int n_quads) {
    int g = blockIdx.x * blockDim.x + threadIdx.x;
    if (g >= n_quads) return;
    float4 v = reinterpret_cast<const float4*>(x)[g];
    __half2 h01(__float2half(v.x), __float2half(v.y));
    __half2 h23(__float2half(v.z), __float2half(v.w));
    uint2 u;
    u.x = *reinterpret_cast<uint32_t*>(&h01);
    u.y = *reinterpret_cast<uint32_t*>(&h23);
    reinterpret_cast<uint2*>(g_xh)[g] = u;
}

// ===========================================================================
// Kernel 4: sparse GEMM. grid=(N/128 [fast], M/256). 256 threads, 8 warps 2x4.
// Warp tile: 64 W-rows x 64 x-rows. k-chunk 64 per stage, 4-stage cp.async.
// ===========================================================================
__device__ __forceinline__ void load_stage(uint32_t sb, int slot, int chunk,
                                           int bw, int bx, int tid) {
    const uint32_t st = sb + slot * STAGE_SZ;
    // A: compressed W, 128 rows x 64 B (32 fp16)
    #pragma unroll
    for (int t = tid; t < 512; t += NTH) {
        int row = t >> 2, c = t & 3;
        uint32_t dst = st + STG_A + row * A_RS + c * 16;
        const __half* src = g_wc + (size_t)(bw * BW + row) * 1024 + chunk * 32 + c * 8;
        cp16(dst, src);
    }
    // B: x, 256 rows x 128 B (64 fp16), xor swizzle
    #pragma unroll
    for (int t = tid; t < 2048; t += NTH) {
        int row = t >> 3, c = t & 7;
        uint32_t so = (uint32_t)(row << 7) + ((c ^ (row & 7)) << 4);
        const __half* src = g_xh + (size_t)(bx * BX + row) * 2048 + chunk * 64 + c * 8;
        cp16(st + STG_B + so, src);
    }
}

__global__ __launch_bounds__(NTH, 1)
void gemm_sp_kernel(const float* __restrict__ bias,
                    float* __restrict__ C,
                    int M, int N, int K) {
    extern __shared__ char smem[];
    const uint32_t sb = smem_u32(smem);
    const int tid = threadIdx.x;
    const int wid = tid >> 5;
    const int lid = tid & 31;
    const int bw = blockIdx.x;       // W block (output cols)
    const int bx = blockIdx.y;       // x block (output rows)

    const int wm = wid >> 2;         // 0..1 -> 64 W-row band
    const int wn = wid & 3;          // 0..3 -> 64 x-row band

    const int a_r  = lid & 15;
    const int a_ch = lid >> 4;
    const int b_r  = (lid & 7) + ((lid >> 4) << 3);
    const int b_ch = (lid >> 3) & 1;
    const int lq   = lid >> 2;       // 0..7 (A row within tile for meta)
    const int lbit = lid & 1;        // k16 half selector for meta

    float acc[4][8][4];
    #pragma unroll
    for (int i = 0; i < 4; i++)
        #pragma unroll
        for (int j = 0; j < 8; j++)
            #pragma unroll
            for (int r = 0; r < 4; r++)
                acc[i][j][r] = 0.0f;

    const int NIT = K / 64;          // 32
    load_stage(sb, 0, 0, bw, bx, tid); CP_COMMIT();
    load_stage(sb, 1, 1, bw, bx, tid); CP_COMMIT();
    load_stage(sb, 2, 2, bw, bx, tid); CP_COMMIT();

    const int tbase = bw * 8 + wm * 4;   // W row-16 tile base index

    for (int i = 0; i < NIT; i++) {
        const int s = i & 3;
        CP_WAIT2();
        __syncthreads();
        const uint32_t A = sb + s * STAGE_SZ + STG_A;
        const uint32_t B = sb + s * STAGE_SZ + STG_B;

        #pragma unroll
        for (int kk = 0; kk < 2; kk++) {
            const int kc = i * 2 + kk;       // global k32 chunk
            uint32_t af[4][4], em[4];
            #pragma unroll
            for (int mt = 0; mt < 4; mt++) {
                int row = wm * 64 + mt * 16 + a_r;
                ldm4(af[mt], A + row * A_RS + kk * 32 + a_ch * 16);
                em[mt] = __ldg(&g_meta[((tbase + mt) * 8 + lq) * 128 + kc * 2 + lbit]);
            }
            #pragma unroll
            for (int nt = 0; nt < 4; nt++) {          // n16 groups of x rows
                int row = wn * 64 + nt * 16 + b_r;
                uint32_t p1[4], p2[4];
                int u1 = kk * 4 + b_ch;               // k[0:16) slab
                int u2 = kk * 4 + 2 + b_ch;           // k[16:32) slab
                ldm4(p1, B + (row << 7) + ((u1 ^ (row & 7)) << 4));
                ldm4(p2, B + (row << 7) + ((u2 ^ (row & 7)) << 4));
                uint32_t bt0[4] = {p1[0], p1[1], p2[0], p2[1]};
                uint32_t bt1[4] = {p1[2], p1[3], p2[2], p2[3]};
                #pragma unroll
                for (int mt = 0; mt < 4; mt++) {
                    mma_sp(acc[mt][nt * 2 + 0], af[mt], bt0, em[mt]);
                    mma_sp(acc[mt][nt * 2 + 1], af[mt], bt1, em[mt]);
                }
            }
        }
        __syncthreads();
        if (i + 3 < NIT) load_stage(sb, (i + 3) & 3, i + 3, bw, bx, tid);
        CP_COMMIT();
    }

    // ---------------- epilogue: transpose via smem, +bias, coalesced --------
    CP_WAIT0();
    __syncthreads();
    float* stg = reinterpret_cast<float*>(smem);   // [256][132]
    #pragma unroll
    for (int mt = 0; mt < 4; mt++)
        #pragma unroll
        for (int nt = 0; nt < 8; nt++) {
            int nloc = wm * 64 + mt * 16 + (lid >> 2);      // W-local row
            int mloc = wn * 64 + nt * 8 + ((lid & 3) << 1); // x-local row
            stg[(mloc + 0) * 132 + nloc]     = acc[mt][nt][0];
            stg[(mloc + 1) * 132 + nloc]     = acc[mt][nt][1];
            stg[(mloc + 0) * 132 + nloc + 8] = acc[mt][nt][2];
            stg[(mloc + 1) * 132 + nloc + 8] = acc[mt][nt][3];
        }
    __syncthreads();
    #pragma unroll
    for (int t = tid; t < 8192; t += NTH) {
        int row = t >> 5;                 // x-local row
        int c4 = (t & 31) << 2;           // W-local col group
        float4 v = *reinterpret_cast<float4*>(&stg[row * 132 + c4]);
        float4 b4 = *reinterpret_cast<const float4*>(bias + bw * BW + c4);
        v.x += b4.x; v.y += b4.y; v.z += b4.z; v.w += b4.w;
        *reinterpret_cast<float4*>(
            C + (size_t)(bx * BX + row) * N + bw * BW + c4) = v;
    }
}

// ===========================================================================
// Launch
// ===========================================================================
extern "C" void kernel_launch(void* const* d_in, const int* in_sizes, int n_in,
                              void* d_out, int out_size) {
    const float* x    = (const float*)d_in[0];  // [M,K]
    const float* w    = (const float*)d_in[1];  // [N,K]
    const float* bias = (const float*)d_in[2];  // [N]
    float* out = (float*)d_out;                 // [M,N]

    const int O = in_sizes[2];          // 2048
    const int H = in_sizes[1] / O;      // 2048
    const int M = in_sizes[0] / H;      // 16384

    int wg = O * H / 4;                 // 1,048,576 groups
    prep_w_kernel<<<(wg + 255) / 256, 256>>>(w, wg);
    int mw = (O / 16) * 8 * (H / 16);   // packed meta words
    pack_meta_kernel<<<(mw + 255) / 256, 256>>>(mw);
    int xg = M * H / 4;
    prep_x_kernel<<<(xg + 255) / 256, 256>>>(x, xg);

    cudaFuncSetAttribute(gemm_sp_kernel,
                         cudaFuncAttributeMaxDynamicSharedMemorySize, SMEM_TOTAL);
    dim3 grid(O / BW, M / BX);          // (16, 64), W-dim fastest
    gemm_sp_kernel<<<grid, NTH, SMEM_TOTAL>>>(bias, out, M, O, H);
}

// round 6
// speedup vs baseline: 6.6727x; 6.6727x over previous
#include <cuda_runtime.h>
#include <cuda_fp16.h>
#include <math.h>
#include <stdint.h>

// ===========================================================================
// out[M,N] = x[M,K] @ (w * nm_mask(w))[N,K]^T + bias[N]
// M=16384, N=2048, K=2048 fp32.
// Single-pass fp16 mma.sync (fp32 accum), rel_err ~2.9e-4.
// CTA tile 128x128, 128 threads (4 warps, 2x2), 3-stage cp.async, 2 CTAs/SM.
// ===========================================================================

__device__ __half g_xh[16384 * 2048];
__device__ __half g_wh[2048 * 2048];

// ---------------- helpers ---------------------------------------------------
__device__ __forceinline__ uint32_t smem_u32(const void* p) {
    uint32_t a;
    asm("{ .reg .u64 t; cvta.to.shared.u64 t, %1; cvt.u32.u64 %0, t; }"
        : "=r"(a) : "l"(p));
    return a;
}
__device__ __forceinline__ void cp16(uint32_t sm, const void* g) {
    asm volatile("cp.async.cg.shared.global [%0], [%1], 16;" :: "r"(sm), "l"(g));
}
#define CP_COMMIT() asm volatile("cp.async.commit_group;" ::: "memory")
#define CP_WAIT1()  asm volatile("cp.async.wait_group 1;"  ::: "memory")
#define CP_WAIT0()  asm volatile("cp.async.wait_group 0;"  ::: "memory")

__device__ __forceinline__ void ldm4(uint32_t r[4], uint32_t addr) {
    asm volatile("ldmatrix.sync.aligned.m8n8.x4.shared.b16 {%0,%1,%2,%3}, [%4];"
                 : "=r"(r[0]), "=r"(r[1]), "=r"(r[2]), "=r"(r[3]) : "r"(addr));
}
__device__ __forceinline__ void mma16816(float c[4], const uint32_t a[4],
                                         const uint32_t b0, const uint32_t b1) {
    asm volatile(
        "mma.sync.aligned.m16n8k16.row.col.f32.f16.f16.f32 "
        "{%0,%1,%2,%3}, {%4,%5,%6,%7}, {%8,%9}, {%0,%1,%2,%3};"
        : "+f"(c[0]), "+f"(c[1]), "+f"(c[2]), "+f"(c[3])
        : "r"(a[0]), "r"(a[1]), "r"(a[2]), "r"(a[3]), "r"(b0), "r"(b1));
}

// ---------------- GEMM config ----------------------------------------------
#define BM 128
#define BN 128
#define BKE 64               // fp16 elems per k-chunk = 128 B/row
#define NTH 128
#define NSTAGE 3
#define STG_A 0              // 16 KB (128 rows x 128 B)
#define STG_B 16384          // 16 KB (128 rows x 128 B)
#define STAGE_SZ 32768
#define SMEM_TOTAL (NSTAGE * STAGE_SZ)   // 96 KB

// ===========================================================================
// Kernel 1: 2:4 mask (stable-argsort semantics) + fp16 convert, 4x ILP
// ===========================================================================
__global__ void prep_w_kernel(const float* __restrict__ w, int n_groups) {
    int base = blockIdx.x * blockDim.x * 4 + threadIdx.x;
    int stride = blockDim.x;
    float4 v[4];
    int idx[4];
    #pragma unroll
    for (int u = 0; u < 4; u++) {
        idx[u] = base + u * stride;
        if (idx[u] < n_groups)
            v[u] = reinterpret_cast<const float4*>(w)[idx[u]];
    }
    #pragma unroll
    for (int u = 0; u < 4; u++) {
        if (idx[u] >= n_groups) continue;
        float vals[4] = {v[u].x, v[u].y, v[u].z, v[u].w};
        float a[4] = {fabsf(v[u].x), fabsf(v[u].y), fabsf(v[u].z), fabsf(v[u].w)};
        int z1 = 0;
        #pragma unroll
        for (int i = 1; i < 4; i++) if (a[i] < a[z1]) z1 = i;
        a[z1] = INFINITY;
        int z2 = 0;
        #pragma unroll
        for (int i = 1; i < 4; i++) if (a[i] < a[z2]) z2 = i;
        vals[z1] = 0.0f;
        vals[z2] = 0.0f;
        __half2 h01(__float2half(vals[0]), __float2half(vals[1]));
        __half2 h23(__float2half(vals[2]), __float2half(vals[3]));
        uint2 o;
        o.x = *reinterpret_cast<uint32_t*>(&h01);
        o.y = *reinterpret_cast<uint32_t*>(&h23);
        reinterpret_cast<uint2*>(g_wh)[idx[u]] = o;
    }
}

// ===========================================================================
// Kernel 2: fp16 convert of x, 4x ILP
// ===========================================================================
__global__ void prep_x_kernel(const float* __restrict__ x, int n_quads) {
    int base = blockIdx.x * blockDim.x * 4 + threadIdx.x;
    int stride = blockDim.x;
    float4 v[4];
    int idx[4];
    #pragma unroll
    for (int u = 0; u < 4; u++) {
        idx[u] = base + u * stride;
        if (idx[u] < n_quads)
            v[u] = reinterpret_cast<const float4*>(x)[idx[u]];
    }
    #pragma unroll
    for (int u = 0; u < 4; u++) {
        if (idx[u] >= n_quads) continue;
        __half2 h01(__float2half(v[u].x), __float2half(v[u].y));
        __half2 h23(__float2half(v[u].z), __float2half(v[u].w));
        uint2 o;
        o.x = *reinterpret_cast<uint32_t*>(&h01);
        o.y = *reinterpret_cast<uint32_t*>(&h23);
        reinterpret_cast<uint2*>(g_xh)[idx[u]] = o;
    }
}

// ===========================================================================
// Kernel 3: fp16 mma.sync GEMM. grid=(N/128 fast, M/128), 128 thr (4 warps 2x2)
// ===========================================================================
__device__ __forceinline__ void load_stage(uint32_t sb, int slot, int chunk,
                                           int bm, int bn, int tid, int K) {
    const int k0 = chunk * BKE;
    const uint32_t st = sb + slot * STAGE_SZ;
    #pragma unroll
    for (int t = tid; t < 1024; t += NTH) {       // A: 128 rows x 8 chunks
        int row = t >> 3, c = t & 7;
        uint32_t so = (uint32_t)(row << 7) + ((c ^ (row & 7)) << 4);
        cp16(st + STG_A + so, g_xh + (size_t)(bm * BM + row) * K + k0 + c * 8);
    }
    #pragma unroll
    for (int t = tid; t < 1024; t += NTH) {       // B: 128 rows x 8 chunks
        int row = t >> 3, c = t & 7;
        uint32_t so = (uint32_t)(row << 7) + ((c ^ (row & 7)) << 4);
        cp16(st + STG_B + so, g_wh + (size_t)(bn * BN + row) * K + k0 + c * 8);
    }
}

__global__ __launch_bounds__(NTH, 2)
void gemm_mma_kernel(const float* __restrict__ bias,
                     float* __restrict__ C,
                     int M, int N, int K) {
    extern __shared__ char smem[];
    const uint32_t sb = smem_u32(smem);
    const int tid = threadIdx.x;
    const int wid = tid >> 5;
    const int lid = tid & 31;
    const int bn = blockIdx.x;
    const int bm = blockIdx.y;

    const int wm = wid >> 1;          // 0..1 -> 64-row band (x rows)
    const int wn = wid & 1;           // 0..1 -> 64-col band (W rows)

    const int a_r  = lid & 15;
    const int a_ch = lid >> 4;
    const int b_r  = (lid & 7) + ((lid >> 4) << 3);
    const int b_ch = (lid >> 3) & 1;

    float acc[4][8][4];
    #pragma unroll
    for (int i = 0; i < 4; i++)
        #pragma unroll
        for (int j = 0; j < 8; j++)
            #pragma unroll
            for (int r = 0; r < 4; r++)
                acc[i][j][r] = 0.0f;

    const int NIT = K / BKE;          // 32
    load_stage(sb, 0, 0, bm, bn, tid, K); CP_COMMIT();
    load_stage(sb, 1, 1, bm, bn, tid, K); CP_COMMIT();

    int s = 0, sl = 2;
    for (int i = 0; i < NIT; i++) {
        CP_WAIT1();
        __syncthreads();
        // issue next loads first (slot sl == slot read at iter i-1, safe after bar)
        if (i + 2 < NIT) load_stage(sb, sl, i + 2, bm, bn, tid, K);
        CP_COMMIT();

        const uint32_t A = sb + s * STAGE_SZ + STG_A;
        const uint32_t B = sb + s * STAGE_SZ + STG_B;
        #pragma unroll
        for (int kk = 0; kk < 4; kk++) {
            uint32_t af[4][4], bf[8][2];
            #pragma unroll
            for (int mt = 0; mt < 4; mt++) {
                int row = wm * 64 + mt * 16 + a_r;
                int c = (kk << 1) + a_ch;
                ldm4(af[mt], A + (row << 7) + ((c ^ (row & 7)) << 4));
            }
            #pragma unroll
            for (int bt = 0; bt < 4; bt++) {
                int row = wn * 64 + bt * 16 + b_r;
                int c = (kk << 1) + b_ch;
                uint32_t rb[4];
                ldm4(rb, B + (row << 7) + ((c ^ (row & 7)) << 4));
                bf[2 * bt + 0][0] = rb[0]; bf[2 * bt + 0][1] = rb[1];
                bf[2 * bt + 1][0] = rb[2]; bf[2 * bt + 1][1] = rb[3];
            }
            #pragma unroll
            for (int mt = 0; mt < 4; mt++)
                #pragma unroll
                for (int nt = 0; nt < 8; nt++)
                    mma16816(acc[mt][nt], af[mt], bf[nt][0], bf[nt][1]);
        }
        s  = (s  == NSTAGE - 1) ? 0 : s + 1;
        sl = (sl == NSTAGE - 1) ? 0 : sl + 1;
    }

    // ---------------- epilogue: regs -> smem -> coalesced +bias stores ------
    CP_WAIT0();
    __syncthreads();
    float* stg = reinterpret_cast<float*>(smem);   // [128][132]
    #pragma unroll
    for (int mt = 0; mt < 4; mt++)
        #pragma unroll
        for (int nt = 0; nt < 8; nt++) {
            int r0 = wm * 64 + mt * 16 + (lid >> 2);
            int col = wn * 64 + nt * 8 + ((lid & 3) << 1);
            *reinterpret_cast<float2*>(&stg[r0 * 132 + col]) =
                make_float2(acc[mt][nt][0], acc[mt][nt][1]);
            *reinterpret_cast<float2*>(&stg[(r0 + 8) * 132 + col]) =
                make_float2(acc[mt][nt][2], acc[mt][nt][3]);
        }
    __syncthreads();
    #pragma unroll
    for (int t = tid; t < 4096; t += NTH) {
        int row = t >> 5;
        int c4 = (t & 31) << 2;
        float4 v = *reinterpret_cast<float4*>(&stg[row * 132 + c4]);
        float4 b4 = *reinterpret_cast<const float4*>(bias + bn * BN + c4);
        v.x += b4.x; v.y += b4.y; v.z += b4.z; v.w += b4.w;
        *reinterpret_cast<float4*>(
            C + (size_t)(bm * BM + row) * N + bn * BN + c4) = v;
    }
}

// ===========================================================================
// Launch
// ===========================================================================
extern "C" void kernel_launch(void* const* d_in, const int* in_sizes, int n_in,
                              void* d_out, int out_size) {
    const float* x    = (const float*)d_in[0];  // [M,K]
    const float* w    = (const float*)d_in[1];  // [N,K]
    const float* bias = (const float*)d_in[2];  // [N]
    float* out = (float*)d_out;                 // [M,N]

    const int O = in_sizes[2];          // 2048
    const int H = in_sizes[1] / O;      // 2048
    const int M = in_sizes[0] / H;      // 16384

    int wg = O * H / 4;
    prep_w_kernel<<<(wg + 1023) / 1024, 256>>>(w, wg);
    int xg = M * H / 4;
    prep_x_kernel<<<(xg + 1023) / 1024, 256>>>(x, xg);

    cudaFuncSetAttribute(gemm_mma_kernel,
                         cudaFuncAttributeMaxDynamicSharedMemorySize, SMEM_TOTAL);
    dim3 grid(O / BN, M / BM);          // (16, 128), N fastest
    gemm_mma_kernel<<<grid, NTH, SMEM_TOTAL>>>(bias, out, M, O, H);
}

// round 7
// speedup vs baseline: 6.9882x; 1.0473x over previous
#include <cuda_runtime.h>
#include <cuda_fp16.h>
#include <math.h>
#include <stdint.h>

// ===========================================================================
// out[M,N] = x[M,K] @ (w * nm_mask(w))[N,K]^T + bias[N]
// M=16384, N=2048, K=2048 fp32.
// Single-pass fp16 mma.sync (fp32 accum), rel_err ~2.9e-4.
// CTA tile 128x128, 128 threads (4 warps 2x2), 3-stage cp.async, 2 CTAs/SM.
// ===========================================================================

__device__ __half g_xh[16384 * 2048];
__device__ __half g_wh[2048 * 2048];

// ---------------- helpers ---------------------------------------------------
__device__ __forceinline__ uint32_t smem_u32(const void* p) {
    uint32_t a;
    asm("{ .reg .u64 t; cvta.to.shared.u64 t, %1; cvt.u32.u64 %0, t; }"
        : "=r"(a) : "l"(p));
    return a;
}
__device__ __forceinline__ void cp16(uint32_t sm, const void* g) {
    asm volatile("cp.async.cg.shared.global [%0], [%1], 16;" :: "r"(sm), "l"(g));
}
#define CP_COMMIT() asm volatile("cp.async.commit_group;" ::: "memory")
#define CP_WAIT1()  asm volatile("cp.async.wait_group 1;"  ::: "memory")
#define CP_WAIT0()  asm volatile("cp.async.wait_group 0;"  ::: "memory")

__device__ __forceinline__ void ldm4(uint32_t r[4], uint32_t addr) {
    asm volatile("ldmatrix.sync.aligned.m8n8.x4.shared.b16 {%0,%1,%2,%3}, [%4];"
                 : "=r"(r[0]), "=r"(r[1]), "=r"(r[2]), "=r"(r[3]) : "r"(addr));
}
__device__ __forceinline__ void mma16816(float c[4], const uint32_t a[4],
                                         const uint32_t b0, const uint32_t b1) {
    asm volatile(
        "mma.sync.aligned.m16n8k16.row.col.f32.f16.f16.f32 "
        "{%0,%1,%2,%3}, {%4,%5,%6,%7}, {%8,%9}, {%0,%1,%2,%3};"
        : "+f"(c[0]), "+f"(c[1]), "+f"(c[2]), "+f"(c[3])
        : "r"(a[0]), "r"(a[1]), "r"(a[2]), "r"(a[3]), "r"(b0), "r"(b1));
}

// ---------------- GEMM config ----------------------------------------------
#define BM 128
#define BN 128
#define BKE 64               // fp16 elems per k-chunk = 128 B/row
#define NTH 128
#define NSTAGE 3
#define STG_A 0              // 16 KB (128 rows x 128 B)
#define STG_B 16384          // 16 KB
#define STAGE_SZ 32768
#define SMEM_TOTAL (NSTAGE * STAGE_SZ)   // 96 KB

// ===========================================================================
// Fused prep: blocks [0, wb) -> weight mask+convert; [wb, ...) -> x convert.
// Each thread handles 8 floats (2 float4 loads -> 1 uint4 store).
// ===========================================================================
__device__ __forceinline__ uint2 mask_quad_to_h4(float4 v) {
    float vals[4] = {v.x, v.y, v.z, v.w};
    float a[4] = {fabsf(v.x), fabsf(v.y), fabsf(v.z), fabsf(v.w)};
    int z1 = 0;
    #pragma unroll
    for (int i = 1; i < 4; i++) if (a[i] < a[z1]) z1 = i;
    a[z1] = INFINITY;
    int z2 = 0;
    #pragma unroll
    for (int i = 1; i < 4; i++) if (a[i] < a[z2]) z2 = i;
    vals[z1] = 0.0f;
    vals[z2] = 0.0f;
    __half2 h01(__float2half(vals[0]), __float2half(vals[1]));
    __half2 h23(__float2half(vals[2]), __float2half(vals[3]));
    uint2 o;
    o.x = *reinterpret_cast<uint32_t*>(&h01);
    o.y = *reinterpret_cast<uint32_t*>(&h23);
    return o;
}
__device__ __forceinline__ uint2 quad_to_h4(float4 v) {
    __half2 h01(__float2half(v.x), __float2half(v.y));
    __half2 h23(__float2half(v.z), __float2half(v.w));
    uint2 o;
    o.x = *reinterpret_cast<uint32_t*>(&h01);
    o.y = *reinterpret_cast<uint32_t*>(&h23);
    return o;
}

__global__ void prep_fused_kernel(const float* __restrict__ w,
                                  const float* __restrict__ x,
                                  int wb, int n_wu, int n_xu) {
    if (blockIdx.x < (unsigned)wb) {
        int u = blockIdx.x * blockDim.x + threadIdx.x;
        if (u >= n_wu) return;
        const float4* wq = reinterpret_cast<const float4*>(w);
        float4 v0 = wq[u * 2 + 0];
        float4 v1 = wq[u * 2 + 1];
        uint2 a = mask_quad_to_h4(v0);
        uint2 b = mask_quad_to_h4(v1);
        uint4 o = make_uint4(a.x, a.y, b.x, b.y);
        reinterpret_cast<uint4*>(g_wh)[u] = o;
    } else {
        int u = (blockIdx.x - wb) * blockDim.x + threadIdx.x;
        if (u >= n_xu) return;
        const float4* xq = reinterpret_cast<const float4*>(x);
        float4 v0 = xq[u * 2 + 0];
        float4 v1 = xq[u * 2 + 1];
        uint2 a = quad_to_h4(v0);
        uint2 b = quad_to_h4(v1);
        uint4 o = make_uint4(a.x, a.y, b.x, b.y);
        reinterpret_cast<uint4*>(g_xh)[u] = o;
    }
}

// ===========================================================================
// GEMM. grid=(N/128 fast, M/128), 128 threads (4 warps 2x2), warp tile 64x64.
// ===========================================================================
__device__ __forceinline__ void load_stage(uint32_t sb, int slot, int chunk,
                                           int bm, int bn, int tid, int K) {
    const int k0 = chunk * BKE;
    const uint32_t st = sb + slot * STAGE_SZ;
    #pragma unroll
    for (int t = tid; t < 1024; t += NTH) {       // A: 128 rows x 8 chunks
        int row = t >> 3, c = t & 7;
        uint32_t so = (uint32_t)(row << 7) + ((c ^ (row & 7)) << 4);
        cp16(st + STG_A + so, g_xh + (size_t)(bm * BM + row) * K + k0 + c * 8);
    }
    #pragma unroll
    for (int t = tid; t < 1024; t += NTH) {       // B: 128 rows x 8 chunks
        int row = t >> 3, c = t & 7;
        uint32_t so = (uint32_t)(row << 7) + ((c ^ (row & 7)) << 4);
        cp16(st + STG_B + so, g_wh + (size_t)(bn * BN + row) * K + k0 + c * 8);
    }
}

struct Frag {
    uint32_t af[4][4];
    uint32_t bf[8][2];
};

__device__ __forceinline__ void load_frags(Frag& f, uint32_t A, uint32_t B,
                                           int kk, int wm, int wn,
                                           int a_r, int a_ch, int b_r, int b_ch) {
    #pragma unroll
    for (int mt = 0; mt < 4; mt++) {
        int row = wm * 64 + mt * 16 + a_r;
        int c = (kk << 1) + a_ch;
        ldm4(f.af[mt], A + (row << 7) + ((c ^ (row & 7)) << 4));
    }
    #pragma unroll
    for (int bt = 0; bt < 4; bt++) {
        int row = wn * 64 + bt * 16 + b_r;
        int c = (kk << 1) + b_ch;
        uint32_t rb[4];
        ldm4(rb, B + (row << 7) + ((c ^ (row & 7)) << 4));
        f.bf[2 * bt + 0][0] = rb[0]; f.bf[2 * bt + 0][1] = rb[1];
        f.bf[2 * bt + 1][0] = rb[2]; f.bf[2 * bt + 1][1] = rb[3];
    }
}

__global__ __launch_bounds__(NTH, 2)
void gemm_mma_kernel(const float* __restrict__ bias,
                     float* __restrict__ C,
                     int M, int N, int K) {
    extern __shared__ char smem[];
    const uint32_t sb = smem_u32(smem);
    const int tid = threadIdx.x;
    const int wid = tid >> 5;
    const int lid = tid & 31;
    const int bn = blockIdx.x;
    const int bm = blockIdx.y;

    const int wm = wid >> 1;
    const int wn = wid & 1;

    const int a_r  = lid & 15;
    const int a_ch = lid >> 4;
    const int b_r  = (lid & 7) + ((lid >> 4) << 3);
    const int b_ch = (lid >> 3) & 1;

    float acc[4][8][4];
    #pragma unroll
    for (int i = 0; i < 4; i++)
        #pragma unroll
        for (int j = 0; j < 8; j++)
            #pragma unroll
            for (int r = 0; r < 4; r++)
                acc[i][j][r] = 0.0f;

    const int NIT = K / BKE;          // 32
    load_stage(sb, 0, 0, bm, bn, tid, K); CP_COMMIT();
    load_stage(sb, 1, 1, bm, bn, tid, K); CP_COMMIT();

    Frag fr[2];
    int s = 0, sl = 2;
    for (int i = 0; i < NIT; i++) {
        CP_WAIT1();
        __syncthreads();
        if (i + 2 < NIT) load_stage(sb, sl, i + 2, bm, bn, tid, K);
        CP_COMMIT();

        const uint32_t A = sb + s * STAGE_SZ + STG_A;
        const uint32_t B = sb + s * STAGE_SZ + STG_B;
        load_frags(fr[0], A, B, 0, wm, wn, a_r, a_ch, b_r, b_ch);
        #pragma unroll
        for (int kk = 0; kk < 4; kk++) {
            if (kk < 3)
                load_frags(fr[(kk + 1) & 1], A, B, kk + 1,
                           wm, wn, a_r, a_ch, b_r, b_ch);
            Frag& f = fr[kk & 1];
            #pragma unroll
            for (int mt = 0; mt < 4; mt++)
                #pragma unroll
                for (int nt = 0; nt < 8; nt++)
                    mma16816(acc[mt][nt], f.af[mt], f.bf[nt][0], f.bf[nt][1]);
        }
        s  = (s  == NSTAGE - 1) ? 0 : s + 1;
        sl = (sl == NSTAGE - 1) ? 0 : sl + 1;
    }

    // ---------------- epilogue ----------------------------------------------
    CP_WAIT0();
    __syncthreads();
    float* stg = reinterpret_cast<float*>(smem);   // [128][132]
    #pragma unroll
    for (int mt = 0; mt < 4; mt++)
        #pragma unroll
        for (int nt = 0; nt < 8; nt++) {
            int r0 = wm * 64 + mt * 16 + (lid >> 2);
            int col = wn * 64 + nt * 8 + ((lid & 3) << 1);
            *reinterpret_cast<float2*>(&stg[r0 * 132 + col]) =
                make_float2(acc[mt][nt][0], acc[mt][nt][1]);
            *reinterpret_cast<float2*>(&stg[(r0 + 8) * 132 + col]) =
                make_float2(acc[mt][nt][2], acc[mt][nt][3]);
        }
    __syncthreads();
    {
        // each thread: 32 rows of one 4-col group; bias loaded once
        int c4 = (tid & 31) << 2;
        int r0 = (tid >> 5) << 5;
        float4 b4 = *reinterpret_cast<const float4*>(bias + bn * BN + c4);
        #pragma unroll
        for (int rr = 0; rr < 32; rr++) {
            int row = r0 + rr;
            float4 v = *reinterpret_cast<float4*>(&stg[row * 132 + c4]);
            v.x += b4.x; v.y += b4.y; v.z += b4.z; v.w += b4.w;
            *reinterpret_cast<float4*>(
                C + (size_t)(bm * BM + row) * N + bn * BN + c4) = v;
        }
    }
}

// ===========================================================================
// Launch
// ===========================================================================
extern "C" void kernel_launch(void* const* d_in, const int* in_sizes, int n_in,
                              void* d_out, int out_size) {
    const float* x    = (const float*)d_in[0];  // [M,K]
    const float* w    = (const float*)d_in[1];  // [N,K]
    const float* bias = (const float*)d_in[2];  // [N]
    float* out = (float*)d_out;                 // [M,N]

    const int O = in_sizes[2];          // 2048
    const int H = in_sizes[1] / O;      // 2048
    const int M = in_sizes[0] / H;      // 16384

    const int n_wu = O * H / 8;         // 8-float units of w
    const int n_xu = M * H / 8;         // 8-float units of x
    const int wb = (n_wu + 255) / 256;
    const int xb = (n_xu + 255) / 256;
    prep_fused_kernel<<<wb + xb, 256>>>(w, x, wb, n_wu, n_xu);

    cudaFuncSetAttribute(gemm_mma_kernel,
                         cudaFuncAttributeMaxDynamicSharedMemorySize, SMEM_TOTAL);
    dim3 grid(O / BN, M / BM);          // (16, 128), N fastest
    gemm_mma_kernel<<<grid, NTH, SMEM_TOTAL>>>(bias, out, M, O, H);
}